// round 5
// baseline (speedup 1.0000x reference)
#include <cuda_runtime.h>
#include <cuda_fp16.h>
#include <cstdint>

#define NMAX 50000
#define EMAX 800000
#define H 64

// Scratch (static device arrays; no dynamic allocation allowed)
__device__ __half          g_h0[NMAX * H];  // fp16 message buffers (ping-pong)
__device__ __half          g_h1[NMAX * H];
__device__ int             g_cnt[NMAX];     // incoming-edge count (excl self loop)
__device__ float           g_dinv[NMAX];
__device__ int             g_off[NMAX];     // CSR offsets
__device__ unsigned short  g_rank[EMAX];    // rank of edge within its dst bucket
__device__ int             g_csr[EMAX];     // CSR-sorted source ids per dst
__device__ float           g_colsum[H];
__device__ int             g_is64;

// decoupled-lookback scan state
__device__ int          g_ticket;
__device__ volatile int g_state[64];
__device__ volatile int g_aggval[64];
__device__ volatile int g_prefval[64];

__device__ __forceinline__ __half* msgbuf(int b) { return b ? g_h1 : g_h0; }

// ---------------------------------------------------------------------------
__global__ void zero_kernel(const unsigned int* __restrict__ w, int N) {
    int i = blockIdx.x * blockDim.x + threadIdx.x;
    if (i < N) g_cnt[i] = 0;
    if (i < H) g_colsum[i] = 0.f;
    if (i < 64) ((int*)g_state)[i] = 0;
    if (i == 0) g_ticket = 0;
    if (blockIdx.x == 0 && threadIdx.x < 32) {
        unsigned int v = w[2 * threadIdx.x + 1] | w[2 * (threadIdx.x + 32) + 1];
        int all0 = __all_sync(0xffffffffu, v == 0u);
        if (threadIdx.x == 0) g_is64 = all0;
    }
}

// Histogram + per-edge rank (atomic return already paid for; 4 edges/thread).
__global__ void hist_kernel(const int* __restrict__ ei, int E) {
    int base = (blockIdx.x * blockDim.x + threadIdx.x) * 4;
    bool is64 = g_is64;
    if (base + 3 < E) {
        int d0 = is64 ? ei[2 * E + 2 * (base + 0)] : ei[E + base + 0];
        int d1 = is64 ? ei[2 * E + 2 * (base + 1)] : ei[E + base + 1];
        int d2 = is64 ? ei[2 * E + 2 * (base + 2)] : ei[E + base + 2];
        int d3 = is64 ? ei[2 * E + 2 * (base + 3)] : ei[E + base + 3];
        int r0 = atomicAdd(&g_cnt[d0], 1);
        int r1 = atomicAdd(&g_cnt[d1], 1);
        int r2 = atomicAdd(&g_cnt[d2], 1);
        int r3 = atomicAdd(&g_cnt[d3], 1);
        g_rank[base + 0] = (unsigned short)r0;
        g_rank[base + 1] = (unsigned short)r1;
        g_rank[base + 2] = (unsigned short)r2;
        g_rank[base + 3] = (unsigned short)r3;
    } else {
        for (int j = 0; j < 4; j++) {
            int e = base + j;
            if (e < E) {
                int d = is64 ? ei[2 * E + 2 * e] : ei[E + e];
                g_rank[e] = (unsigned short)atomicAdd(&g_cnt[d], 1);
            }
        }
    }
}

// ---------------------------------------------------------------------------
// Single-kernel exclusive scan (decoupled lookback, ticket-ordered).
// ---------------------------------------------------------------------------
__global__ void scan_kernel(int N) {
    __shared__ int s_bid;
    __shared__ int s_warp[8];
    __shared__ int s_exc;
    int t = threadIdx.x;
    if (t == 0) s_bid = atomicAdd(&g_ticket, 1);
    __syncthreads();
    int bid = s_bid;

    int base = bid * 1024 + t * 4;
    int v[4], tsum = 0;
#pragma unroll
    for (int j = 0; j < 4; j++) {
        int idx = base + j;
        v[j] = (idx < N) ? g_cnt[idx] : 0;
        tsum += v[j];
    }
    int lane = t & 31, w = t >> 5;
    int x = tsum;
#pragma unroll
    for (int o = 1; o < 32; o <<= 1) {
        int y = __shfl_up_sync(0xffffffffu, x, o);
        if (lane >= o) x += y;
    }
    if (lane == 31) s_warp[w] = x;
    __syncthreads();

    if (t == 0) {
        int total = 0;
#pragma unroll
        for (int i = 0; i < 8; i++) { int tmp = s_warp[i]; s_warp[i] = total; total += tmp; }
        int exc = 0;
        if (bid == 0) {
            g_prefval[0] = total;
            __threadfence();
            g_state[0] = 2;
        } else {
            g_aggval[bid] = total;
            __threadfence();
            g_state[bid] = 1;
            int i = bid - 1;
            while (true) {
                int st;
                while ((st = g_state[i]) == 0) { }
                if (st == 2) { exc += g_prefval[i]; break; }
                exc += g_aggval[i];
                i--;
            }
            g_prefval[bid] = exc + total;
            __threadfence();
            g_state[bid] = 2;
        }
        s_exc = exc;
    }
    __syncthreads();

    int run = x - tsum + s_warp[w] + s_exc;
#pragma unroll
    for (int j = 0; j < 4; j++) {
        int idx = base + j;
        if (idx < N) {
            g_off[idx]  = run;
            g_dinv[idx] = rsqrtf((float)(v[j] + 1));   // +1 self loop
            run += v[j];
        }
    }
}

// Atomic-free CSR fill: pos = off[d] + rank[e].
__global__ void fill_kernel(const int* __restrict__ ei, int E) {
    int base = (blockIdx.x * blockDim.x + threadIdx.x) * 4;
    bool is64 = g_is64;
#pragma unroll
    for (int j = 0; j < 4; j++) {
        int e = base + j;
        if (e < E) {
            int s, d;
            if (is64) { s = ei[2 * e]; d = ei[2 * E + 2 * e]; }
            else      { s = ei[e];     d = ei[E + e]; }
            g_csr[g_off[d] + (int)g_rank[e]] = s;
        }
    }
}

// ---------------------------------------------------------------------------
// Shared helpers
// ---------------------------------------------------------------------------
__device__ __forceinline__ void acc16(float* a, uint4 r0, uint4 r1) {
    const unsigned int rr[8] = {r0.x, r0.y, r0.z, r0.w, r1.x, r1.y, r1.z, r1.w};
#pragma unroll
    for (int q = 0; q < 8; q++) {
        __half2 h = *reinterpret_cast<const __half2*>(&rr[q]);
        float2 f = __half22float2(h);
        a[2 * q]     += f.x;
        a[2 * q + 1] += f.y;
    }
}

// Gather + accumulate all messages for node gn into a[16] (features
// lane*16..lane*16+15). Includes the self message. 4 edges unrolled (MLP=8).
__device__ __forceinline__ void gather_node(float* a, const __half* src,
                                            int gn, int lane) {
    const uint4* gh = (const uint4*)src;   // 8 uint4 per node row
#pragma unroll
    for (int j = 0; j < 16; j++) a[j] = 0.f;
    {   // self
        uint4 r0 = __ldg(gh + (size_t)gn * 8 + lane * 2);
        uint4 r1 = __ldg(gh + (size_t)gn * 8 + lane * 2 + 1);
        acc16(a, r0, r1);
    }
    int e = g_off[gn];
    int end = e + g_cnt[gn];
    for (; e + 4 <= end; e += 4) {
        int s0 = __ldg(&g_csr[e]);
        int s1 = __ldg(&g_csr[e + 1]);
        int s2 = __ldg(&g_csr[e + 2]);
        int s3 = __ldg(&g_csr[e + 3]);
        uint4 a0 = __ldg(gh + (size_t)s0 * 8 + lane * 2);
        uint4 a1 = __ldg(gh + (size_t)s0 * 8 + lane * 2 + 1);
        uint4 b0 = __ldg(gh + (size_t)s1 * 8 + lane * 2);
        uint4 b1 = __ldg(gh + (size_t)s1 * 8 + lane * 2 + 1);
        uint4 c0 = __ldg(gh + (size_t)s2 * 8 + lane * 2);
        uint4 c1 = __ldg(gh + (size_t)s2 * 8 + lane * 2 + 1);
        uint4 d0 = __ldg(gh + (size_t)s3 * 8 + lane * 2);
        uint4 d1 = __ldg(gh + (size_t)s3 * 8 + lane * 2 + 1);
        acc16(a, a0, a1);
        acc16(a, b0, b1);
        acc16(a, c0, c1);
        acc16(a, d0, d1);
    }
    for (; e < end; e++) {
        int s = __ldg(&g_csr[e]);
        uint4 r0 = __ldg(gh + (size_t)s * 8 + lane * 2);
        uint4 r1 = __ldg(gh + (size_t)s * 8 + lane * 2 + 1);
        acc16(a, r0, r1);
    }
}

// ---------------------------------------------------------------------------
// Layer 1 GEMM: x[N,10] @ W1[10,64], scale by dinv, write fp16 msgs to buf 0.
// ---------------------------------------------------------------------------
__global__ __launch_bounds__(256) void gemm1_kernel(const float* __restrict__ X,
                                                    const float* __restrict__ W,
                                                    int N) {
    __shared__ float xs[64][12];
    __shared__ float ws[10][64];
    int node0 = blockIdx.x * 64;
    int t = threadIdx.x;

    for (int i = t; i < 640; i += 256) ws[i >> 6][i & 63] = W[i];
    for (int i = t; i < 640; i += 256) {
        int n = i / 10, k = i - n * 10;
        int gn = node0 + n;
        xs[n][k] = (gn < N) ? X[gn * 10 + k] : 0.f;
    }
    __syncthreads();

    int tx = t & 15, ty = t >> 4;
    float acc[4][4];
#pragma unroll
    for (int i = 0; i < 4; i++)
#pragma unroll
        for (int j = 0; j < 4; j++) acc[i][j] = 0.f;

#pragma unroll
    for (int k = 0; k < 10; k++) {
        float4 wv = *(const float4*)&ws[k][tx * 4];
#pragma unroll
        for (int i = 0; i < 4; i++) {
            float xa = xs[ty * 4 + i][k];
            acc[i][0] = fmaf(xa, wv.x, acc[i][0]);
            acc[i][1] = fmaf(xa, wv.y, acc[i][1]);
            acc[i][2] = fmaf(xa, wv.z, acc[i][2]);
            acc[i][3] = fmaf(xa, wv.w, acc[i][3]);
        }
    }

    __half* dst = msgbuf(0);
#pragma unroll
    for (int i = 0; i < 4; i++) {
        int gn = node0 + ty * 4 + i;
        if (gn < N) {
            float di = g_dinv[gn];
            __half2* hp = (__half2*)(dst + (size_t)gn * H + tx * 4);
            hp[0] = __floats2half2_rn(acc[i][0] * di, acc[i][1] * di);
            hp[1] = __floats2half2_rn(acc[i][2] * di, acc[i][3] * di);
        }
    }
}

// ---------------------------------------------------------------------------
// Fused aggregate + epilogue + GEMM for layers 2/3.
// Reads messages from buffer SRC, writes new messages to buffer 1-SRC.
// (Double buffering: other blocks may still be reading SRC while we write.)
// Phase 1: 4 threads/node gather+sum messages of the block's 64 nodes,
//          apply relu(agg*dinv + bias_prev), store to smem xs[node][feat].
// Phase 2: 64x64x64 GEMM with W, scale by dinv, write fp16 messages.
// ---------------------------------------------------------------------------
__global__ __launch_bounds__(256) void fused_kernel(const float* __restrict__ W,
                                                    const float* __restrict__ bias_prev,
                                                    int src_buf, int N) {
    __shared__ float xs[64][68];
    __shared__ float ws[64][64];
    __shared__ float bsh[64];

    int node0 = blockIdx.x * 64;
    int t = threadIdx.x;

    for (int i = t; i < 4096; i += 256) ws[i >> 6][i & 63] = W[i];
    if (t < 64) bsh[t] = bias_prev[t];
    __syncthreads();

    const __half* src = msgbuf(src_buf);
    __half* dst = msgbuf(1 - src_buf);

    int n = t >> 2, lane = t & 3;
    int gn = node0 + n;
    if (gn < N) {
        float a[16];
        gather_node(a, src, gn, lane);
        float di = g_dinv[gn];
#pragma unroll
        for (int j = 0; j < 16; j++)
            xs[n][lane * 16 + j] = fmaxf(fmaf(a[j], di, bsh[lane * 16 + j]), 0.f);
    } else {
#pragma unroll
        for (int j = 0; j < 16; j++) xs[n][lane * 16 + j] = 0.f;
    }
    __syncthreads();

    int tx = t & 15, ty = t >> 4;
    float acc[4][4];
#pragma unroll
    for (int i = 0; i < 4; i++)
#pragma unroll
        for (int j = 0; j < 4; j++) acc[i][j] = 0.f;

#pragma unroll
    for (int k = 0; k < 64; k++) {
        float4 wv = *(const float4*)&ws[k][tx * 4];
#pragma unroll
        for (int i = 0; i < 4; i++) {
            float xa = xs[ty * 4 + i][k];
            acc[i][0] = fmaf(xa, wv.x, acc[i][0]);
            acc[i][1] = fmaf(xa, wv.y, acc[i][1]);
            acc[i][2] = fmaf(xa, wv.z, acc[i][2]);
            acc[i][3] = fmaf(xa, wv.w, acc[i][3]);
        }
    }

#pragma unroll
    for (int i = 0; i < 4; i++) {
        int g = node0 + ty * 4 + i;
        if (g < N) {
            float di = g_dinv[g];
            __half2* hp = (__half2*)(dst + (size_t)g * H + tx * 4);
            hp[0] = __floats2half2_rn(acc[i][0] * di, acc[i][1] * di);
            hp[1] = __floats2half2_rn(acc[i][2] * di, acc[i][3] * di);
        }
    }
}

// ---------------------------------------------------------------------------
// Final aggregate (layer 3) fused with mean pooling column sums.
// ---------------------------------------------------------------------------
__global__ __launch_bounds__(256) void aggfinal_kernel(int src_buf, int N) {
    __shared__ float s_col[H];
    if (threadIdx.x < H) s_col[threadIdx.x] = 0.f;
    __syncthreads();

    const __half* src = msgbuf(src_buf);
    int idx = blockIdx.x * blockDim.x + threadIdx.x;
    int node = idx >> 2, lane = idx & 3;
    if (node < N) {
        float a[16];
        gather_node(a, src, node, lane);
        float di = g_dinv[node];
#pragma unroll
        for (int j = 0; j < 16; j++)
            atomicAdd(&s_col[lane * 16 + j], a[j] * di);
    }
    __syncthreads();
    if (threadIdx.x < H) atomicAdd(&g_colsum[threadIdx.x], s_col[threadIdx.x]);
}

// out = (colsum/N + b3) . fcW + fcb
__global__ void final_kernel(const float* __restrict__ b3,
                             const float* __restrict__ fcW,
                             const float* __restrict__ fcb,
                             float* __restrict__ out, int N) {
    int f = threadIdx.x;  // 64 threads
    float v = (g_colsum[f] / (float)N + b3[f]) * fcW[f];
#pragma unroll
    for (int o = 16; o > 0; o >>= 1) v += __shfl_down_sync(0xffffffffu, v, o);
    __shared__ float p[2];
    if ((f & 31) == 0) p[f >> 5] = v;
    __syncthreads();
    if (f == 0) out[0] = p[0] + p[1] + fcb[0];
}

extern "C" void kernel_launch(void* const* d_in, const int* in_sizes, int n_in,
                              void* d_out, int out_size) {
    const float* x   = (const float*)d_in[0];
    const void*  ei  = d_in[1];
    const float* W1  = (const float*)d_in[2];
    const float* b1  = (const float*)d_in[3];
    const float* W2  = (const float*)d_in[4];
    const float* b2  = (const float*)d_in[5];
    const float* W3  = (const float*)d_in[6];
    const float* b3  = (const float*)d_in[7];
    const float* fcW = (const float*)d_in[8];
    const float* fcb = (const float*)d_in[9];
    float* out = (float*)d_out;

    int FIN1 = in_sizes[2] / H;      // 10
    int N = in_sizes[0] / FIN1;      // 50000
    int E = in_sizes[1] / 2;         // 800000

    int SB = (N + 1023) / 1024;              // scan blocks (<=64)
    int eblocks = (E + 1023) / 1024;         // 4 edges/thread
    int gblocks = (N + 63) / 64;
    int fblocks = (N * 4 + 255) / 256;

    zero_kernel<<<(N + 255) / 256, 256>>>((const unsigned int*)ei, N);
    hist_kernel<<<eblocks, 256>>>((const int*)ei, E);
    scan_kernel<<<SB, 256>>>(N);
    fill_kernel<<<eblocks, 256>>>((const int*)ei, E);

    gemm1_kernel<<<gblocks, 256>>>(x, W1, N);            // -> buf 0
    fused_kernel<<<gblocks, 256>>>(W2, b1, 0, N);        // buf0 -> buf1
    fused_kernel<<<gblocks, 256>>>(W3, b2, 1, N);        // buf1 -> buf0
    aggfinal_kernel<<<fblocks, 256>>>(0, N);             // buf0 -> colsum
    final_kernel<<<1, 64>>>(b3, fcW, fcb, out, N);
}